// round 15
// baseline (speedup 1.0000x reference)
#include <cuda_runtime.h>
#include <cuda_fp16.h>
#include <math.h>

#define BB 8
#define LL 2048
#define DD 512
#define HH 1024
#define CC 64
#define MM (BB*LL)   // 16384
#define NSEG 32
#define SEGL 64

// ---------------- scratch (static device globals; no allocations) ----------------
__device__ float  g_x  [MM*DD];
__device__ __half g_xn [MM*DD];
__device__ __half g_h  [MM*HH];
__device__ __half g_abc[MM*192];     // tanh projections (fp16)
__device__ __half g_w1t[2*HH*DD];
__device__ __half g_w2t[2*DD*HH];
__device__ __half g_wt [192*DD];
__device__ float  g_seg[BB*NSEG*6*64];

// ---------------- PTX helpers ----------------
__device__ __forceinline__ void cp16g(void* dst, const void* src) {
    unsigned d = (unsigned)__cvta_generic_to_shared(dst);
    asm volatile("cp.async.cg.shared.global [%0], [%1], 16;\n" :: "r"(d), "l"(src));
}
__device__ __forceinline__ void cp_commit() {
    asm volatile("cp.async.commit_group;\n");
}
template<int N>
__device__ __forceinline__ void cp_wait() {
    asm volatile("cp.async.wait_group %0;\n" :: "n"(N));
}
__device__ __forceinline__ void ldsm4(unsigned& r0, unsigned& r1,
                                      unsigned& r2, unsigned& r3, unsigned addr) {
    asm volatile("ldmatrix.sync.aligned.m8n8.x4.shared.b16 {%0,%1,%2,%3}, [%4];"
                 : "=r"(r0), "=r"(r1), "=r"(r2), "=r"(r3) : "r"(addr));
}
__device__ __forceinline__ void mma16816(float* acc, const unsigned* a, const unsigned* b) {
    asm volatile(
        "mma.sync.aligned.m16n8k16.row.col.f32.f16.f16.f32 "
        "{%0,%1,%2,%3}, {%4,%5,%6,%7}, {%8,%9}, {%0,%1,%2,%3};"
        : "+f"(acc[0]), "+f"(acc[1]), "+f"(acc[2]), "+f"(acc[3])
        : "r"(a[0]), "r"(a[1]), "r"(a[2]), "r"(a[3]), "r"(b[0]), "r"(b[1]));
}

// ---------------- warp-per-row fused embedding + first LN (fp16 xn out) ----------
__global__ void embed_ln_kernel(const int* __restrict__ ids,
                                const float* __restrict__ tok,
                                const float* __restrict__ pos,
                                const float* __restrict__ lw,
                                const float* __restrict__ lb,
                                float* __restrict__ x,
                                __half* __restrict__ xn) {
    int wid = threadIdx.x >> 5, lane = threadIdx.x & 31;
    int t = blockIdx.x * 8 + wid;
    int id = ids[t];
    int l  = t & (LL - 1);
    const float4* tr = (const float4*)(tok + (size_t)id * DD);
    const float4* pr = (const float4*)(pos + (size_t)l  * DD);
    float4 v[4];
    float s = 0.f, s2 = 0.f;
    #pragma unroll
    for (int j = 0; j < 4; j++) {
        float4 a = tr[j * 32 + lane];
        float4 p = pr[j * 32 + lane];
        v[j].x = a.x + p.x; v[j].y = a.y + p.y;
        v[j].z = a.z + p.z; v[j].w = a.w + p.w;
        s  += v[j].x + v[j].y + v[j].z + v[j].w;
        s2 += v[j].x*v[j].x + v[j].y*v[j].y + v[j].z*v[j].z + v[j].w*v[j].w;
    }
    float4* xr = (float4*)(x + (size_t)t * DD);
    #pragma unroll
    for (int j = 0; j < 4; j++) xr[j * 32 + lane] = v[j];
    #pragma unroll
    for (int o = 16; o; o >>= 1) {
        s  += __shfl_xor_sync(0xffffffffu, s,  o);
        s2 += __shfl_xor_sync(0xffffffffu, s2, o);
    }
    float mean = s * (1.0f / DD);
    float var  = s2 * (1.0f / DD) - mean * mean;
    float inv  = rsqrtf(var + 1e-5f);
    __half* outr = xn + (size_t)t * DD;
    #pragma unroll
    for (int j = 0; j < 4; j++) {
        int c = (j * 32 + lane) * 4;
        float4 wv = *(const float4*)(lw + c);
        float4 bv = *(const float4*)(lb + c);
        __half2 h0 = __floats2half2_rn((v[j].x - mean) * inv * wv.x + bv.x,
                                       (v[j].y - mean) * inv * wv.y + bv.y);
        __half2 h1 = __floats2half2_rn((v[j].z - mean) * inv * wv.z + bv.z,
                                       (v[j].w - mean) * inv * wv.w + bv.w);
        uint2 pk; pk.x = *(unsigned*)&h0; pk.y = *(unsigned*)&h1;
        *(uint2*)(outr + c) = pk;
    }
}

// ---------------- warp-per-row LayerNorm -> fp16 out ----------------
__global__ void ln_kernel(const float* __restrict__ x,
                          const float* __restrict__ w,
                          const float* __restrict__ b,
                          __half* __restrict__ out) {
    int wid = threadIdx.x >> 5, lane = threadIdx.x & 31;
    size_t row = (size_t)blockIdx.x * 8 + wid;
    const float4* xr = (const float4*)(x + row * DD);
    float4 v[4];
    float s = 0.f, s2 = 0.f;
    #pragma unroll
    for (int j = 0; j < 4; j++) {
        v[j] = xr[j * 32 + lane];
        s  += v[j].x + v[j].y + v[j].z + v[j].w;
        s2 += v[j].x*v[j].x + v[j].y*v[j].y + v[j].z*v[j].z + v[j].w*v[j].w;
    }
    #pragma unroll
    for (int o = 16; o; o >>= 1) {
        s  += __shfl_xor_sync(0xffffffffu, s,  o);
        s2 += __shfl_xor_sync(0xffffffffu, s2, o);
    }
    float mean = s * (1.0f / DD);
    float var  = s2 * (1.0f / DD) - mean * mean;
    float inv  = rsqrtf(var + 1e-5f);
    __half* outr = out + row * DD;
    #pragma unroll
    for (int j = 0; j < 4; j++) {
        int c = (j * 32 + lane) * 4;
        float4 wv = *(const float4*)(w + c);
        float4 bv = *(const float4*)(b + c);
        __half2 h0 = __floats2half2_rn((v[j].x - mean) * inv * wv.x + bv.x,
                                       (v[j].y - mean) * inv * wv.y + bv.y);
        __half2 h1 = __floats2half2_rn((v[j].z - mean) * inv * wv.z + bv.z,
                                       (v[j].w - mean) * inv * wv.w + bv.w);
        uint2 pk; pk.x = *(unsigned*)&h0; pk.y = *(unsigned*)&h1;
        *(uint2*)(outr + c) = pk;
    }
}

// ------- merged weight prep: z<2 transp w1 ; z<4 transp w2 ; z==4 pack -------
__global__ void prep_kernel(const float* __restrict__ w1,
                            const float* __restrict__ w2,
                            const float* __restrict__ Wa,
                            const float* __restrict__ Wb,
                            const float* __restrict__ Wc,
                            __half* __restrict__ w1t,
                            __half* __restrict__ w2t,
                            __half* __restrict__ wt) {
    int z = blockIdx.z;
    int tx = threadIdx.x, ty = threadIdx.y;
    if (z == 4) {
        int bx = blockIdx.y * 32 + blockIdx.x;
        if (bx >= 128) return;
        int i = bx * 256 + ty * 32 + tx;
        int d = i >> 6, c = i & 63;
        wt[(size_t)c * DD + d]         = __float2half_rn(Wa[i]);
        wt[(size_t)(64 + c) * DD + d]  = __float2half_rn(Wb[i]);
        wt[(size_t)(128 + c) * DD + d] = __float2half_rn(Wc[i]);
        return;
    }
    __shared__ __half t[32][33];
    const float* in; __half* out; int K, N;
    if (z < 2) {
        if (blockIdx.y >= DD / 32) return;
        K = DD; N = HH;
        in  = w1  + (size_t)z * DD * HH;
        out = w1t + (size_t)z * HH * DD;
    } else {
        if (blockIdx.x >= DD / 32) return;
        K = HH; N = DD;
        in  = w2  + (size_t)(z - 2) * HH * DD;
        out = w2t + (size_t)(z - 2) * DD * HH;
    }
    int n0 = blockIdx.x * 32, k0 = blockIdx.y * 32;
    #pragma unroll
    for (int i = 0; i < 32; i += 8)
        t[ty + i][tx] = __float2half_rn(in[(size_t)(k0 + ty + i) * N + n0 + tx]);
    __syncthreads();
    #pragma unroll
    for (int i = 0; i < 32; i += 8)
        out[(size_t)(n0 + ty + i) * K + k0 + tx] = t[tx][ty + i];
}

// ======= h16gemm2: 128xBN, BK=64, ldmatrix, 2-stage cp.async, OCC CTAs/SM =======
// EPI: 1 bias+exact GELU -> half, 2 bias+residual add -> fp32, 3 tanh -> half
template<int BN, int EPI, int OCC>
__global__ __launch_bounds__(256, OCC)
void h16gemm2(const __half* __restrict__ A, const __half* __restrict__ Bw,
              const float* __restrict__ bias, void* __restrict__ Cv,
              int K, int ldc) {
    constexpr int BM = 128, BK = 64;
    constexpr int LDA = BK + 8;
    constexpr int NI  = BN / 16;
    constexpr int NP  = BN / 32;
    constexpr int ASZ = BM * LDA;
    constexpr int BSZ = BN * LDA;
    constexpr int STG = ASZ + BSZ;

    extern __shared__ __half smh[];

    const int tid  = threadIdx.x;
    const int lane = tid & 31, warp = tid >> 5;
    const int wr   = warp >> 1, wc = warp & 1;
    const int g    = lane >> 2, tig = lane & 3;
    const int rowBase = blockIdx.y * BM;
    const int colBase = blockIdx.x * BN;

    float acc[2][NI][4];
    #pragma unroll
    for (int mi = 0; mi < 2; mi++)
        #pragma unroll
        for (int ni = 0; ni < NI; ni++)
            #pragma unroll
            for (int r = 0; r < 4; r++) acc[mi][ni][r] = 0.f;

    unsigned aBase[2], bBase[NP];
    {
        unsigned s0 = (unsigned)__cvta_generic_to_shared(smh);
        #pragma unroll
        for (int mi = 0; mi < 2; mi++) {
            int row = wr * 32 + mi * 16 + (lane & 15);
            int col = (lane >> 4) << 3;
            aBase[mi] = s0 + (row * LDA + col) * 2;
        }
        #pragma unroll
        for (int p = 0; p < NP; p++) {
            int row = wc * (BN / 2) + p * 16 + ((lane >> 4) << 3) + (lane & 7);
            int col = ((lane >> 3) & 1) << 3;
            bBase[p] = s0 + (ASZ + row * LDA + col) * 2;
        }
    }

    const int nt = K / BK;

    auto issue = [&](int kt) {
        __half* As = smh + (kt & 1) * STG;
        __half* Bs = As + ASZ;
        int k0 = kt * BK;
        #pragma unroll
        for (int it = 0; it < (BM * 8) / 256; it++) {
            int idx = tid + it * 256;
            int r = idx >> 3, u = (idx & 7) << 3;
            cp16g(As + r * LDA + u, A + (size_t)(rowBase + r) * K + k0 + u);
        }
        #pragma unroll
        for (int it = 0; it < (BN * 8) / 256; it++) {
            int idx = tid + it * 256;
            int r = idx >> 3, u = (idx & 7) << 3;
            cp16g(Bs + r * LDA + u, Bw + (size_t)(colBase + r) * K + k0 + u);
        }
    };

    issue(0); cp_commit();

    for (int kt = 0; kt < nt; kt++) {
        cp_wait<0>();
        __syncthreads();
        if (kt + 1 < nt) { issue(kt + 1); cp_commit(); }

        unsigned stOff = (unsigned)((kt & 1) * STG * 2);

        #pragma unroll
        for (int kk = 0; kk < BK; kk += 16) {
            unsigned af[2][4];
            #pragma unroll
            for (int mi = 0; mi < 2; mi++)
                ldsm4(af[mi][0], af[mi][1], af[mi][2], af[mi][3],
                      aBase[mi] + stOff + kk * 2);
            unsigned bf[NI][2];
            #pragma unroll
            for (int p = 0; p < NP; p++)
                ldsm4(bf[2*p][0], bf[2*p][1], bf[2*p+1][0], bf[2*p+1][1],
                      bBase[p] + stOff + kk * 2);
            #pragma unroll
            for (int mi = 0; mi < 2; mi++)
                #pragma unroll
                for (int ni = 0; ni < NI; ni++)
                    mma16816(acc[mi][ni], af[mi], bf[ni]);
        }
    }

    #pragma unroll
    for (int mi = 0; mi < 2; mi++) {
        #pragma unroll
        for (int ni = 0; ni < NI; ni++) {
            int row = rowBase + wr * 32 + mi * 16 + g;
            int col = colBase + wc * (BN / 2) + ni * 8 + tig * 2;
            #pragma unroll
            for (int half_ = 0; half_ < 2; half_++) {
                int r = row + half_ * 8;
                float v0 = acc[mi][ni][half_ * 2 + 0];
                float v1 = acc[mi][ni][half_ * 2 + 1];
                if (EPI == 1) {
                    v0 += bias[col];  v1 += bias[col + 1];
                    __half* p = (__half*)Cv + (size_t)r * ldc + col;
                    *(__half2*)p = __floats2half2_rn(v0 * normcdff(v0),
                                                     v1 * normcdff(v1));
                } else if (EPI == 2) {
                    float2* p = (float2*)((float*)Cv + (size_t)r * ldc + col);
                    float2 old = *p;
                    float2 o; o.x = old.x + v0 + bias[col];
                    o.y = old.y + v1 + bias[col + 1];
                    *p = o;
                } else {                             // tanh -> fp16
                    __half* p = (__half*)Cv + (size_t)r * ldc + col;
                    *(__half2*)p = __floats2half2_rn(tanhf(v0), tanhf(v1));
                }
            }
        }
    }
}

// ------- fused u = abc @ class^T + segment scan (abc fp16 in) -------
__global__ __launch_bounds__(256, 2)
void uscan_kernel(const __half* __restrict__ abc,
                  const float* __restrict__ cA,
                  const float* __restrict__ cB,
                  const float* __restrict__ cC,
                  float* __restrict__ segout) {
    extern __shared__ float us[];
    float* At = us;                    // 64*68
    float* Ct = us + 64*68;            // 64*68
    float* Ut = us + 2*64*68;          // 64*192
    const int tid = threadIdx.x;
    const int t0  = blockIdx.x * 64;
    const int tx = tid & 15, ty = tid >> 4;

    for (int gi = 0; gi < 3; gi++) {
        const float* cls = (gi == 0) ? cA : (gi == 1) ? cB : cC;
        for (int i = tid; i < 4096; i += 256) {
            int c = i >> 6, r = i & 63;
            Ct[r * 68 + c] = cls[i];
        }
        // fp16 abc: each thread handles 2 consecutive r (half2 load), 2048 pairs
        for (int i = tid; i < 2048; i += 256) {
            int tok = i >> 5, rp = (i & 31) * 2;
            __half2 h = *(const __half2*)(abc + (size_t)(t0 + tok) * 192 + gi * 64 + rp);
            float2 f = __half22float2(h);
            At[(rp    ) * 68 + tok] = f.x;
            At[(rp + 1) * 68 + tok] = f.y;
        }
        __syncthreads();
        float acc[4][4];
        #pragma unroll
        for (int i = 0; i < 4; i++)
            #pragma unroll
            for (int j = 0; j < 4; j++) acc[i][j] = 0.f;
        for (int r = 0; r < 64; r++) {
            float4 a = *(const float4*)(At + r * 68 + ty * 4);
            float4 b = *(const float4*)(Ct + r * 68 + tx * 4);
            float av[4] = {a.x, a.y, a.z, a.w};
            float bv[4] = {b.x, b.y, b.z, b.w};
            #pragma unroll
            for (int i = 0; i < 4; i++)
                #pragma unroll
                for (int j = 0; j < 4; j++)
                    acc[i][j] = fmaf(av[i], bv[j], acc[i][j]);
        }
        #pragma unroll
        for (int i = 0; i < 4; i++)
            #pragma unroll
            for (int j = 0; j < 4; j++)
                Ut[(ty * 4 + i) * 192 + gi * 64 + tx * 4 + j] = acc[i][j];
        __syncthreads();
    }

    if (tid < 64) {
        int c = tid;
        float pA = 0.f, pB = 0.f, pT = 0.f, AB = 0.f, BC = 0.f, S = 0.f, Cs = 0.f;
        int nTok = ((t0 & (LL - 1)) == LL - SEGL) ? SEGL - 1 : SEGL;
        #pragma unroll 4
        for (int i = 0; i < nTok; i++) {
            float va = Ut[i * 192 + c];
            float vb = Ut[i * 192 + 64 + c];
            float vc = Ut[i * 192 + 128 + c];
            S  = fmaf(vc, pT, S);
            BC = fmaf(vc, pB, BC);
            pT = fmaf(vb, pA, pT);
            AB = fmaf(vb, pA, AB);
            pB += vb;
            pA += va;
            Cs += vc;
        }
        int b = t0 >> 11;
        int s = (t0 & (LL - 1)) >> 6;
        float* o = segout + ((size_t)(b * NSEG + s) * 6) * 64 + c;
        o[0]   = pA;  o[64]  = pB;  o[128] = Cs;
        o[192] = AB;  o[256] = BC;  o[320] = S;
    }
}

// -------- phase 2: combine segments + fused query LN + query head --------
__global__ void scan_combine_kernel(const float* __restrict__ segout,
                                    const float* __restrict__ x,
                                    const float* __restrict__ lnw,
                                    const float* __restrict__ lnb,
                                    const float* __restrict__ Wq,
                                    const float* __restrict__ bq,
                                    float* __restrict__ out) {
    __shared__ float qn[DD];
    __shared__ float red[2][2];
    int b = blockIdx.x, c = threadIdx.x;
    int warp = c >> 5, lane = c & 31;

    const float* xr = x + ((size_t)b * LL + LL - 1) * DD;
    float4 v0 = ((const float4*)xr)[c * 2];
    float4 v1 = ((const float4*)xr)[c * 2 + 1];
    float s  = v0.x + v0.y + v0.z + v0.w + v1.x + v1.y + v1.z + v1.w;
    float s2 = v0.x*v0.x + v0.y*v0.y + v0.z*v0.z + v0.w*v0.w
             + v1.x*v1.x + v1.y*v1.y + v1.z*v1.z + v1.w*v1.w;
    #pragma unroll
    for (int o = 16; o; o >>= 1) {
        s  += __shfl_down_sync(0xffffffffu, s,  o);
        s2 += __shfl_down_sync(0xffffffffu, s2, o);
    }
    if (!lane) { red[0][warp] = s; red[1][warp] = s2; }
    __syncthreads();
    s  = red[0][0] + red[0][1];
    s2 = red[1][0] + red[1][1];
    float mean = s * (1.0f / DD);
    float var  = s2 * (1.0f / DD) - mean * mean;
    float inv  = rsqrtf(var + 1e-5f);
    {
        int k = c * 8;
        float4 w0 = *(const float4*)(lnw + k);
        float4 w1 = *(const float4*)(lnw + k + 4);
        float4 b0 = *(const float4*)(lnb + k);
        float4 b1 = *(const float4*)(lnb + k + 4);
        qn[k + 0] = (v0.x - mean) * inv * w0.x + b0.x;
        qn[k + 1] = (v0.y - mean) * inv * w0.y + b0.y;
        qn[k + 2] = (v0.z - mean) * inv * w0.z + b0.z;
        qn[k + 3] = (v0.w - mean) * inv * w0.w + b0.w;
        qn[k + 4] = (v1.x - mean) * inv * w1.x + b1.x;
        qn[k + 5] = (v1.y - mean) * inv * w1.y + b1.y;
        qn[k + 6] = (v1.z - mean) * inv * w1.z + b1.z;
        qn[k + 7] = (v1.w - mean) * inv * w1.w + b1.w;
    }
    __syncthreads();

    float PA = 0.f, PAB = 0.f, PE = 0.f, total = 0.f;
    #pragma unroll
    for (int sg = 0; sg < NSEG; sg++) {
        const float* o = segout + ((size_t)(b * NSEG + sg) * 6) * 64 + c;
        float A = o[0], B = o[64], C = o[128], AB = o[192], BC = o[256], S = o[320];
        total += S + C * (PE + PAB) + BC * PA;
        PE  = fmaf(B, PA, PE);
        PAB += AB;
        PA  += A;
    }

    float q = 0.f;
    #pragma unroll 8
    for (int k = 0; k < DD; k++) q = fmaf(qn[k], Wq[k * CC + c], q);
    const float inv_den = (float)(6.0 / (2047.0 * 2046.0 * 2045.0));
    out[b * CC + c] = total * inv_den + q + bq[c];
}

// ---------------- launch ----------------
extern "C" void kernel_launch(void* const* d_in, const int* in_sizes, int n_in,
                              void* d_out, int out_size) {
    const int*   ids       = (const int*)  d_in[0];
    const float* tok_emb   = (const float*)d_in[1];
    const float* pos_emb   = (const float*)d_in[2];
    const float* stem_ln_w = (const float*)d_in[3];
    const float* stem_ln_b = (const float*)d_in[4];
    const float* stem_w1   = (const float*)d_in[5];
    const float* stem_b1   = (const float*)d_in[6];
    const float* stem_w2   = (const float*)d_in[7];
    const float* stem_b2   = (const float*)d_in[8];
    const float* role_ln_w = (const float*)d_in[9];
    const float* role_ln_b = (const float*)d_in[10];
    const float* Wa        = (const float*)d_in[11];
    const float* Wb        = (const float*)d_in[12];
    const float* Wc        = (const float*)d_in[13];
    const float* class_a   = (const float*)d_in[14];
    const float* class_b   = (const float*)d_in[15];
    const float* class_c   = (const float*)d_in[16];
    const float* query_ln_w= (const float*)d_in[17];
    const float* query_ln_b= (const float*)d_in[18];
    const float* Wq        = (const float*)d_in[19];
    const float* bq        = (const float*)d_in[20];
    float* out = (float*)d_out;

    float *xp, *segp;
    __half *xnp, *hp, *abcp, *w1t, *w2t, *wt;
    cudaGetSymbolAddress((void**)&xp,   g_x);
    cudaGetSymbolAddress((void**)&xnp,  g_xn);
    cudaGetSymbolAddress((void**)&hp,   g_h);
    cudaGetSymbolAddress((void**)&abcp, g_abc);
    cudaGetSymbolAddress((void**)&w1t,  g_w1t);
    cudaGetSymbolAddress((void**)&w2t,  g_w2t);
    cudaGetSymbolAddress((void**)&wt,   g_wt);
    cudaGetSymbolAddress((void**)&segp, g_seg);

    constexpr int SM64 = 2 * (128 * 72 + 64 * 72) * 2;    // 55296 B
    constexpr int SMUS = (2 * 64 * 68 + 64 * 192) * 4;    // 83968 B
    cudaFuncSetAttribute((const void*)h16gemm2<64,1,4>,
                         cudaFuncAttributeMaxDynamicSharedMemorySize, SM64);
    cudaFuncSetAttribute((const void*)h16gemm2<64,2,4>,
                         cudaFuncAttributeMaxDynamicSharedMemorySize, SM64);
    cudaFuncSetAttribute((const void*)h16gemm2<64,3,4>,
                         cudaFuncAttributeMaxDynamicSharedMemorySize, SM64);
    cudaFuncSetAttribute((const void*)uscan_kernel,
                         cudaFuncAttributeMaxDynamicSharedMemorySize, SMUS);

    // 0. merged weight prep
    prep_kernel<<<dim3(32, 32, 5), dim3(32, 8)>>>(
        stem_w1, stem_w2, Wa, Wb, Wc, w1t, w2t, wt);

    // 1. embedding + LN0 fused (warp-per-row)
    embed_ln_kernel<<<MM/8, 256>>>(ids, tok_emb, pos_emb, stem_ln_w, stem_ln_b, xp, xnp);

    // 2. stem blocks (BN=64 tiles, 4 CTA/SM)
    for (int i = 0; i < 2; i++) {
        if (i > 0)
            ln_kernel<<<MM/8, 256>>>(xp, stem_ln_w + i*DD, stem_ln_b + i*DD, xnp);
        h16gemm2<64,1,4><<<dim3(HH/64, MM/128), 256, SM64>>>(
            xnp, w1t + (size_t)i*HH*DD, stem_b1 + i*HH, hp, DD, HH);
        h16gemm2<64,2,4><<<dim3(DD/64, MM/128), 256, SM64>>>(
            hp, w2t + (size_t)i*DD*HH, stem_b2 + i*DD, xp, HH, DD);
    }

    // 3. role LN (warp-per-row, fp16 out)
    ln_kernel<<<MM/8, 256>>>(xp, role_ln_w, role_ln_b, xnp);

    // 4. abc = tanh(xn @ [Wa|Wb|Wc]) -> fp16
    h16gemm2<64,3,4><<<dim3(3, MM/128), 256, SM64>>>(xnp, wt, nullptr, abcp, DD, 192);

    // 5+7a. fused u GEMM + per-segment triplet scan (fp16 abc in)
    uscan_kernel<<<MM/64, 256, SMUS>>>(abcp, class_a, class_b, class_c, segp);

    // 7b. combine segments + fused query LN + query head
    scan_combine_kernel<<<BB, CC>>>(segp, xp, query_ln_w, query_ln_b, Wq, bq, out);
}

// round 16
// speedup vs baseline: 1.0007x; 1.0007x over previous
#include <cuda_runtime.h>
#include <cuda_fp16.h>
#include <math.h>

#define BB 8
#define LL 2048
#define DD 512
#define HH 1024
#define CC 64
#define MM (BB*LL)   // 16384
#define NSEG 32
#define SEGL 64

// ---------------- scratch (static device globals; no allocations) ----------------
__device__ float  g_x  [MM*DD];
__device__ __half g_xn [MM*DD];
__device__ __half g_h  [MM*HH];
__device__ float  g_abc[MM*192];     // tanh projections (fp32)
__device__ __half g_w1t[2*HH*DD];
__device__ __half g_w2t[2*DD*HH];
__device__ __half g_wt [192*DD];
__device__ float  g_seg[BB*NSEG*6*64];

// ---------------- PTX helpers ----------------
__device__ __forceinline__ void cp16g(void* dst, const void* src) {
    unsigned d = (unsigned)__cvta_generic_to_shared(dst);
    asm volatile("cp.async.cg.shared.global [%0], [%1], 16;\n" :: "r"(d), "l"(src));
}
__device__ __forceinline__ void cp_commit() {
    asm volatile("cp.async.commit_group;\n");
}
template<int N>
__device__ __forceinline__ void cp_wait() {
    asm volatile("cp.async.wait_group %0;\n" :: "n"(N));
}
__device__ __forceinline__ void ldsm4(unsigned& r0, unsigned& r1,
                                      unsigned& r2, unsigned& r3, unsigned addr) {
    asm volatile("ldmatrix.sync.aligned.m8n8.x4.shared.b16 {%0,%1,%2,%3}, [%4];"
                 : "=r"(r0), "=r"(r1), "=r"(r2), "=r"(r3) : "r"(addr));
}
__device__ __forceinline__ void mma16816(float* acc, const unsigned* a, const unsigned* b) {
    asm volatile(
        "mma.sync.aligned.m16n8k16.row.col.f32.f16.f16.f32 "
        "{%0,%1,%2,%3}, {%4,%5,%6,%7}, {%8,%9}, {%0,%1,%2,%3};"
        : "+f"(acc[0]), "+f"(acc[1]), "+f"(acc[2]), "+f"(acc[3])
        : "r"(a[0]), "r"(a[1]), "r"(a[2]), "r"(a[3]), "r"(b[0]), "r"(b[1]));
}

// ---------------- warp-per-row fused embedding + first LN (fp16 xn out) ----------
__global__ void embed_ln_kernel(const int* __restrict__ ids,
                                const float* __restrict__ tok,
                                const float* __restrict__ pos,
                                const float* __restrict__ lw,
                                const float* __restrict__ lb,
                                float* __restrict__ x,
                                __half* __restrict__ xn) {
    int wid = threadIdx.x >> 5, lane = threadIdx.x & 31;
    int t = blockIdx.x * 8 + wid;
    int id = ids[t];
    int l  = t & (LL - 1);
    const float4* tr = (const float4*)(tok + (size_t)id * DD);
    const float4* pr = (const float4*)(pos + (size_t)l  * DD);
    float4 v[4];
    float s = 0.f, s2 = 0.f;
    #pragma unroll
    for (int j = 0; j < 4; j++) {
        float4 a = tr[j * 32 + lane];
        float4 p = pr[j * 32 + lane];
        v[j].x = a.x + p.x; v[j].y = a.y + p.y;
        v[j].z = a.z + p.z; v[j].w = a.w + p.w;
        s  += v[j].x + v[j].y + v[j].z + v[j].w;
        s2 += v[j].x*v[j].x + v[j].y*v[j].y + v[j].z*v[j].z + v[j].w*v[j].w;
    }
    float4* xr = (float4*)(x + (size_t)t * DD);
    #pragma unroll
    for (int j = 0; j < 4; j++) xr[j * 32 + lane] = v[j];
    #pragma unroll
    for (int o = 16; o; o >>= 1) {
        s  += __shfl_xor_sync(0xffffffffu, s,  o);
        s2 += __shfl_xor_sync(0xffffffffu, s2, o);
    }
    float mean = s * (1.0f / DD);
    float var  = s2 * (1.0f / DD) - mean * mean;
    float inv  = rsqrtf(var + 1e-5f);
    __half* outr = xn + (size_t)t * DD;
    #pragma unroll
    for (int j = 0; j < 4; j++) {
        int c = (j * 32 + lane) * 4;
        float4 wv = *(const float4*)(lw + c);
        float4 bv = *(const float4*)(lb + c);
        __half2 h0 = __floats2half2_rn((v[j].x - mean) * inv * wv.x + bv.x,
                                       (v[j].y - mean) * inv * wv.y + bv.y);
        __half2 h1 = __floats2half2_rn((v[j].z - mean) * inv * wv.z + bv.z,
                                       (v[j].w - mean) * inv * wv.w + bv.w);
        uint2 pk; pk.x = *(unsigned*)&h0; pk.y = *(unsigned*)&h1;
        *(uint2*)(outr + c) = pk;
    }
}

// ---------------- warp-per-row LayerNorm -> fp16 out ----------------
__global__ void ln_kernel(const float* __restrict__ x,
                          const float* __restrict__ w,
                          const float* __restrict__ b,
                          __half* __restrict__ out) {
    int wid = threadIdx.x >> 5, lane = threadIdx.x & 31;
    size_t row = (size_t)blockIdx.x * 8 + wid;
    const float4* xr = (const float4*)(x + row * DD);
    float4 v[4];
    float s = 0.f, s2 = 0.f;
    #pragma unroll
    for (int j = 0; j < 4; j++) {
        v[j] = xr[j * 32 + lane];
        s  += v[j].x + v[j].y + v[j].z + v[j].w;
        s2 += v[j].x*v[j].x + v[j].y*v[j].y + v[j].z*v[j].z + v[j].w*v[j].w;
    }
    #pragma unroll
    for (int o = 16; o; o >>= 1) {
        s  += __shfl_xor_sync(0xffffffffu, s,  o);
        s2 += __shfl_xor_sync(0xffffffffu, s2, o);
    }
    float mean = s * (1.0f / DD);
    float var  = s2 * (1.0f / DD) - mean * mean;
    float inv  = rsqrtf(var + 1e-5f);
    __half* outr = out + row * DD;
    #pragma unroll
    for (int j = 0; j < 4; j++) {
        int c = (j * 32 + lane) * 4;
        float4 wv = *(const float4*)(w + c);
        float4 bv = *(const float4*)(b + c);
        __half2 h0 = __floats2half2_rn((v[j].x - mean) * inv * wv.x + bv.x,
                                       (v[j].y - mean) * inv * wv.y + bv.y);
        __half2 h1 = __floats2half2_rn((v[j].z - mean) * inv * wv.z + bv.z,
                                       (v[j].w - mean) * inv * wv.w + bv.w);
        uint2 pk; pk.x = *(unsigned*)&h0; pk.y = *(unsigned*)&h1;
        *(uint2*)(outr + c) = pk;
    }
}

// ------- merged weight prep: z<2 transp w1 ; z<4 transp w2 ; z==4 pack -------
__global__ void prep_kernel(const float* __restrict__ w1,
                            const float* __restrict__ w2,
                            const float* __restrict__ Wa,
                            const float* __restrict__ Wb,
                            const float* __restrict__ Wc,
                            __half* __restrict__ w1t,
                            __half* __restrict__ w2t,
                            __half* __restrict__ wt) {
    int z = blockIdx.z;
    int tx = threadIdx.x, ty = threadIdx.y;
    if (z == 4) {
        int bx = blockIdx.y * 32 + blockIdx.x;
        if (bx >= 128) return;
        int i = bx * 256 + ty * 32 + tx;
        int d = i >> 6, c = i & 63;
        wt[(size_t)c * DD + d]         = __float2half_rn(Wa[i]);
        wt[(size_t)(64 + c) * DD + d]  = __float2half_rn(Wb[i]);
        wt[(size_t)(128 + c) * DD + d] = __float2half_rn(Wc[i]);
        return;
    }
    __shared__ __half t[32][33];
    const float* in; __half* out; int K, N;
    if (z < 2) {
        if (blockIdx.y >= DD / 32) return;
        K = DD; N = HH;
        in  = w1  + (size_t)z * DD * HH;
        out = w1t + (size_t)z * HH * DD;
    } else {
        if (blockIdx.x >= DD / 32) return;
        K = HH; N = DD;
        in  = w2  + (size_t)(z - 2) * HH * DD;
        out = w2t + (size_t)(z - 2) * DD * HH;
    }
    int n0 = blockIdx.x * 32, k0 = blockIdx.y * 32;
    #pragma unroll
    for (int i = 0; i < 32; i += 8)
        t[ty + i][tx] = __float2half_rn(in[(size_t)(k0 + ty + i) * N + n0 + tx]);
    __syncthreads();
    #pragma unroll
    for (int i = 0; i < 32; i += 8)
        out[(size_t)(n0 + ty + i) * K + k0 + tx] = t[tx][ty + i];
}

// ======= h16gemm2: 128xBN, BK=64, ldmatrix, 2-stage cp.async, OCC CTAs/SM =======
// EPI: 1 bias+exact GELU -> half, 2 bias+residual add -> fp32, 3 tanh -> fp32
template<int BN, int EPI, int OCC>
__global__ __launch_bounds__(256, OCC)
void h16gemm2(const __half* __restrict__ A, const __half* __restrict__ Bw,
              const float* __restrict__ bias, void* __restrict__ Cv,
              int K, int ldc) {
    constexpr int BM = 128, BK = 64;
    constexpr int LDA = BK + 8;
    constexpr int NI  = BN / 16;
    constexpr int NP  = BN / 32;
    constexpr int ASZ = BM * LDA;
    constexpr int BSZ = BN * LDA;
    constexpr int STG = ASZ + BSZ;

    extern __shared__ __half smh[];

    const int tid  = threadIdx.x;
    const int lane = tid & 31, warp = tid >> 5;
    const int wr   = warp >> 1, wc = warp & 1;
    const int g    = lane >> 2, tig = lane & 3;
    const int rowBase = blockIdx.y * BM;
    const int colBase = blockIdx.x * BN;

    float acc[2][NI][4];
    #pragma unroll
    for (int mi = 0; mi < 2; mi++)
        #pragma unroll
        for (int ni = 0; ni < NI; ni++)
            #pragma unroll
            for (int r = 0; r < 4; r++) acc[mi][ni][r] = 0.f;

    unsigned aBase[2], bBase[NP];
    {
        unsigned s0 = (unsigned)__cvta_generic_to_shared(smh);
        #pragma unroll
        for (int mi = 0; mi < 2; mi++) {
            int row = wr * 32 + mi * 16 + (lane & 15);
            int col = (lane >> 4) << 3;
            aBase[mi] = s0 + (row * LDA + col) * 2;
        }
        #pragma unroll
        for (int p = 0; p < NP; p++) {
            int row = wc * (BN / 2) + p * 16 + ((lane >> 4) << 3) + (lane & 7);
            int col = ((lane >> 3) & 1) << 3;
            bBase[p] = s0 + (ASZ + row * LDA + col) * 2;
        }
    }

    const int nt = K / BK;

    auto issue = [&](int kt) {
        __half* As = smh + (kt & 1) * STG;
        __half* Bs = As + ASZ;
        int k0 = kt * BK;
        #pragma unroll
        for (int it = 0; it < (BM * 8) / 256; it++) {
            int idx = tid + it * 256;
            int r = idx >> 3, u = (idx & 7) << 3;
            cp16g(As + r * LDA + u, A + (size_t)(rowBase + r) * K + k0 + u);
        }
        #pragma unroll
        for (int it = 0; it < (BN * 8) / 256; it++) {
            int idx = tid + it * 256;
            int r = idx >> 3, u = (idx & 7) << 3;
            cp16g(Bs + r * LDA + u, Bw + (size_t)(colBase + r) * K + k0 + u);
        }
    };

    issue(0); cp_commit();

    for (int kt = 0; kt < nt; kt++) {
        cp_wait<0>();
        __syncthreads();
        if (kt + 1 < nt) { issue(kt + 1); cp_commit(); }

        unsigned stOff = (unsigned)((kt & 1) * STG * 2);

        #pragma unroll
        for (int kk = 0; kk < BK; kk += 16) {
            unsigned af[2][4];
            #pragma unroll
            for (int mi = 0; mi < 2; mi++)
                ldsm4(af[mi][0], af[mi][1], af[mi][2], af[mi][3],
                      aBase[mi] + stOff + kk * 2);
            unsigned bf[NI][2];
            #pragma unroll
            for (int p = 0; p < NP; p++)
                ldsm4(bf[2*p][0], bf[2*p][1], bf[2*p+1][0], bf[2*p+1][1],
                      bBase[p] + stOff + kk * 2);
            #pragma unroll
            for (int mi = 0; mi < 2; mi++)
                #pragma unroll
                for (int ni = 0; ni < NI; ni++)
                    mma16816(acc[mi][ni], af[mi], bf[ni]);
        }
    }

    #pragma unroll
    for (int mi = 0; mi < 2; mi++) {
        #pragma unroll
        for (int ni = 0; ni < NI; ni++) {
            int row = rowBase + wr * 32 + mi * 16 + g;
            int col = colBase + wc * (BN / 2) + ni * 8 + tig * 2;
            #pragma unroll
            for (int half_ = 0; half_ < 2; half_++) {
                int r = row + half_ * 8;
                float v0 = acc[mi][ni][half_ * 2 + 0];
                float v1 = acc[mi][ni][half_ * 2 + 1];
                if (EPI == 1) {
                    v0 += bias[col];  v1 += bias[col + 1];
                    __half* p = (__half*)Cv + (size_t)r * ldc + col;
                    *(__half2*)p = __floats2half2_rn(v0 * normcdff(v0),
                                                     v1 * normcdff(v1));
                } else if (EPI == 2) {
                    float2* p = (float2*)((float*)Cv + (size_t)r * ldc + col);
                    float2 old = *p;
                    float2 o; o.x = old.x + v0 + bias[col];
                    o.y = old.y + v1 + bias[col + 1];
                    *p = o;
                } else {                             // tanh -> fp32
                    float2* p = (float2*)((float*)Cv + (size_t)r * ldc + col);
                    float2 o; o.x = tanhf(v0); o.y = tanhf(v1);
                    *p = o;
                }
            }
        }
    }
}

// ------- fused u = abc @ class^T + segment scan (one 64-token segment/block) -------
__global__ __launch_bounds__(256, 2)
void uscan_kernel(const float* __restrict__ abc,
                  const float* __restrict__ cA,
                  const float* __restrict__ cB,
                  const float* __restrict__ cC,
                  float* __restrict__ segout) {
    extern __shared__ float us[];
    float* At = us;                    // 64*68
    float* Ct = us + 64*68;            // 64*68
    float* Ut = us + 2*64*68;          // 64*192
    const int tid = threadIdx.x;
    const int t0  = blockIdx.x * 64;
    const int tx = tid & 15, ty = tid >> 4;

    for (int gi = 0; gi < 3; gi++) {
        const float* cls = (gi == 0) ? cA : (gi == 1) ? cB : cC;
        // class matrix: float4 loads (1024 elements = 256 float4)
        for (int i = tid; i < 1024; i += 256) {
            int c = i >> 4, r4 = (i & 15) * 4;
            float4 v = *(const float4*)(cls + c * 64 + r4);
            Ct[(r4 + 0) * 68 + c] = v.x;
            Ct[(r4 + 1) * 68 + c] = v.y;
            Ct[(r4 + 2) * 68 + c] = v.z;
            Ct[(r4 + 3) * 68 + c] = v.w;
        }
        // abc tile: float4 loads, transposed scatter to smem
        for (int i = tid; i < 1024; i += 256) {
            int tok = i >> 4, r4 = (i & 15) * 4;
            float4 v = *(const float4*)(abc + (size_t)(t0 + tok) * 192 + gi * 64 + r4);
            At[(r4 + 0) * 68 + tok] = v.x;
            At[(r4 + 1) * 68 + tok] = v.y;
            At[(r4 + 2) * 68 + tok] = v.z;
            At[(r4 + 3) * 68 + tok] = v.w;
        }
        __syncthreads();
        float acc[4][4];
        #pragma unroll
        for (int i = 0; i < 4; i++)
            #pragma unroll
            for (int j = 0; j < 4; j++) acc[i][j] = 0.f;
        for (int r = 0; r < 64; r++) {
            float4 a = *(const float4*)(At + r * 68 + ty * 4);
            float4 b = *(const float4*)(Ct + r * 68 + tx * 4);
            float av[4] = {a.x, a.y, a.z, a.w};
            float bv[4] = {b.x, b.y, b.z, b.w};
            #pragma unroll
            for (int i = 0; i < 4; i++)
                #pragma unroll
                for (int j = 0; j < 4; j++)
                    acc[i][j] = fmaf(av[i], bv[j], acc[i][j]);
        }
        #pragma unroll
        for (int i = 0; i < 4; i++)
            #pragma unroll
            for (int j = 0; j < 4; j++)
                Ut[(ty * 4 + i) * 192 + gi * 64 + tx * 4 + j] = acc[i][j];
        __syncthreads();
    }

    if (tid < 64) {
        int c = tid;
        float pA = 0.f, pB = 0.f, pT = 0.f, AB = 0.f, BC = 0.f, S = 0.f, Cs = 0.f;
        int nTok = ((t0 & (LL - 1)) == LL - SEGL) ? SEGL - 1 : SEGL;
        #pragma unroll 4
        for (int i = 0; i < nTok; i++) {
            float va = Ut[i * 192 + c];
            float vb = Ut[i * 192 + 64 + c];
            float vc = Ut[i * 192 + 128 + c];
            S  = fmaf(vc, pT, S);
            BC = fmaf(vc, pB, BC);
            pT = fmaf(vb, pA, pT);
            AB = fmaf(vb, pA, AB);
            pB += vb;
            pA += va;
            Cs += vc;
        }
        int b = t0 >> 11;
        int s = (t0 & (LL - 1)) >> 6;
        float* o = segout + ((size_t)(b * NSEG + s) * 6) * 64 + c;
        o[0]   = pA;  o[64]  = pB;  o[128] = Cs;
        o[192] = AB;  o[256] = BC;  o[320] = S;
    }
}

// -------- phase 2: combine segments + fused query LN + query head --------
__global__ void scan_combine_kernel(const float* __restrict__ segout,
                                    const float* __restrict__ x,
                                    const float* __restrict__ lnw,
                                    const float* __restrict__ lnb,
                                    const float* __restrict__ Wq,
                                    const float* __restrict__ bq,
                                    float* __restrict__ out) {
    __shared__ float qn[DD];
    __shared__ float red[2][2];
    int b = blockIdx.x, c = threadIdx.x;
    int warp = c >> 5, lane = c & 31;

    const float* xr = x + ((size_t)b * LL + LL - 1) * DD;
    float4 v0 = ((const float4*)xr)[c * 2];
    float4 v1 = ((const float4*)xr)[c * 2 + 1];
    float s  = v0.x + v0.y + v0.z + v0.w + v1.x + v1.y + v1.z + v1.w;
    float s2 = v0.x*v0.x + v0.y*v0.y + v0.z*v0.z + v0.w*v0.w
             + v1.x*v1.x + v1.y*v1.y + v1.z*v1.z + v1.w*v1.w;
    #pragma unroll
    for (int o = 16; o; o >>= 1) {
        s  += __shfl_down_sync(0xffffffffu, s,  o);
        s2 += __shfl_down_sync(0xffffffffu, s2, o);
    }
    if (!lane) { red[0][warp] = s; red[1][warp] = s2; }
    __syncthreads();
    s  = red[0][0] + red[0][1];
    s2 = red[1][0] + red[1][1];
    float mean = s * (1.0f / DD);
    float var  = s2 * (1.0f / DD) - mean * mean;
    float inv  = rsqrtf(var + 1e-5f);
    {
        int k = c * 8;
        float4 w0 = *(const float4*)(lnw + k);
        float4 w1 = *(const float4*)(lnw + k + 4);
        float4 b0 = *(const float4*)(lnb + k);
        float4 b1 = *(const float4*)(lnb + k + 4);
        qn[k + 0] = (v0.x - mean) * inv * w0.x + b0.x;
        qn[k + 1] = (v0.y - mean) * inv * w0.y + b0.y;
        qn[k + 2] = (v0.z - mean) * inv * w0.z + b0.z;
        qn[k + 3] = (v0.w - mean) * inv * w0.w + b0.w;
        qn[k + 4] = (v1.x - mean) * inv * w1.x + b1.x;
        qn[k + 5] = (v1.y - mean) * inv * w1.y + b1.y;
        qn[k + 6] = (v1.z - mean) * inv * w1.z + b1.z;
        qn[k + 7] = (v1.w - mean) * inv * w1.w + b1.w;
    }
    __syncthreads();

    float PA = 0.f, PAB = 0.f, PE = 0.f, total = 0.f;
    #pragma unroll
    for (int sg = 0; sg < NSEG; sg++) {
        const float* o = segout + ((size_t)(b * NSEG + sg) * 6) * 64 + c;
        float A = o[0], B = o[64], C = o[128], AB = o[192], BC = o[256], S = o[320];
        total += S + C * (PE + PAB) + BC * PA;
        PE  = fmaf(B, PA, PE);
        PAB += AB;
        PA  += A;
    }

    float q = 0.f;
    #pragma unroll 8
    for (int k = 0; k < DD; k++) q = fmaf(qn[k], Wq[k * CC + c], q);
    const float inv_den = (float)(6.0 / (2047.0 * 2046.0 * 2045.0));
    out[b * CC + c] = total * inv_den + q + bq[c];
}

// ---------------- launch ----------------
extern "C" void kernel_launch(void* const* d_in, const int* in_sizes, int n_in,
                              void* d_out, int out_size) {
    const int*   ids       = (const int*)  d_in[0];
    const float* tok_emb   = (const float*)d_in[1];
    const float* pos_emb   = (const float*)d_in[2];
    const float* stem_ln_w = (const float*)d_in[3];
    const float* stem_ln_b = (const float*)d_in[4];
    const float* stem_w1   = (const float*)d_in[5];
    const float* stem_b1   = (const float*)d_in[6];
    const float* stem_w2   = (const float*)d_in[7];
    const float* stem_b2   = (const float*)d_in[8];
    const float* role_ln_w = (const float*)d_in[9];
    const float* role_ln_b = (const float*)d_in[10];
    const float* Wa        = (const float*)d_in[11];
    const float* Wb        = (const float*)d_in[12];
    const float* Wc        = (const float*)d_in[13];
    const float* class_a   = (const float*)d_in[14];
    const float* class_b   = (const float*)d_in[15];
    const float* class_c   = (const float*)d_in[16];
    const float* query_ln_w= (const float*)d_in[17];
    const float* query_ln_b= (const float*)d_in[18];
    const float* Wq        = (const float*)d_in[19];
    const float* bq        = (const float*)d_in[20];
    float* out = (float*)d_out;

    float *xp, *abcp, *segp;
    __half *xnp, *hp, *w1t, *w2t, *wt;
    cudaGetSymbolAddress((void**)&xp,   g_x);
    cudaGetSymbolAddress((void**)&xnp,  g_xn);
    cudaGetSymbolAddress((void**)&hp,   g_h);
    cudaGetSymbolAddress((void**)&abcp, g_abc);
    cudaGetSymbolAddress((void**)&w1t,  g_w1t);
    cudaGetSymbolAddress((void**)&w2t,  g_w2t);
    cudaGetSymbolAddress((void**)&wt,   g_wt);
    cudaGetSymbolAddress((void**)&segp, g_seg);

    constexpr int SM64 = 2 * (128 * 72 + 64 * 72) * 2;    // 55296 B
    constexpr int SMUS = (2 * 64 * 68 + 64 * 192) * 4;    // 83968 B
    cudaFuncSetAttribute((const void*)h16gemm2<64,1,4>,
                         cudaFuncAttributeMaxDynamicSharedMemorySize, SM64);
    cudaFuncSetAttribute((const void*)h16gemm2<64,2,4>,
                         cudaFuncAttributeMaxDynamicSharedMemorySize, SM64);
    cudaFuncSetAttribute((const void*)h16gemm2<64,3,4>,
                         cudaFuncAttributeMaxDynamicSharedMemorySize, SM64);
    cudaFuncSetAttribute((const void*)uscan_kernel,
                         cudaFuncAttributeMaxDynamicSharedMemorySize, SMUS);

    // 0. merged weight prep
    prep_kernel<<<dim3(32, 32, 5), dim3(32, 8)>>>(
        stem_w1, stem_w2, Wa, Wb, Wc, w1t, w2t, wt);

    // 1. embedding + LN0 fused (warp-per-row)
    embed_ln_kernel<<<MM/8, 256>>>(ids, tok_emb, pos_emb, stem_ln_w, stem_ln_b, xp, xnp);

    // 2. stem blocks (BN=64 tiles, 4 CTA/SM)
    for (int i = 0; i < 2; i++) {
        if (i > 0)
            ln_kernel<<<MM/8, 256>>>(xp, stem_ln_w + i*DD, stem_ln_b + i*DD, xnp);
        h16gemm2<64,1,4><<<dim3(HH/64, MM/128), 256, SM64>>>(
            xnp, w1t + (size_t)i*HH*DD, stem_b1 + i*HH, hp, DD, HH);
        h16gemm2<64,2,4><<<dim3(DD/64, MM/128), 256, SM64>>>(
            hp, w2t + (size_t)i*DD*HH, stem_b2 + i*DD, xp, HH, DD);
    }

    // 3. role LN (warp-per-row, fp16 out)
    ln_kernel<<<MM/8, 256>>>(xp, role_ln_w, role_ln_b, xnp);

    // 4. abc = tanh(xn @ [Wa|Wb|Wc]) -> fp32
    h16gemm2<64,3,4><<<dim3(3, MM/128), 256, SM64>>>(xnp, wt, nullptr, abcp, DD, 192);

    // 5+7a. fused u GEMM + per-segment triplet scan (float4 fills)
    uscan_kernel<<<MM/64, 256, SMUS>>>(abcp, class_a, class_b, class_c, segp);

    // 7b. combine segments + fused query LN + query head
    scan_combine_kernel<<<BB, CC>>>(segp, xp, query_ln_w, query_ln_b, Wq, bq, out);
}

// round 17
// speedup vs baseline: 1.0132x; 1.0125x over previous
#include <cuda_runtime.h>
#include <cuda_fp16.h>
#include <math.h>

#define BB 8
#define LL 2048
#define DD 512
#define HH 1024
#define CC 64
#define MM (BB*LL)   // 16384
#define NSEG 32
#define SEGL 64

// ---------------- scratch (static device globals; no allocations) ----------------
__device__ float  g_x  [MM*DD];
__device__ __half g_xn [MM*DD];
__device__ __half g_h  [MM*HH];
__device__ float  g_abc[MM*192];     // tanh projections (fp32)
__device__ __half g_w1t[2*HH*DD];
__device__ __half g_w2t[2*DD*HH];
__device__ __half g_wt [192*DD];
__device__ float  g_seg[BB*NSEG*6*64];

// ---------------- PTX helpers ----------------
__device__ __forceinline__ void cp16g(void* dst, const void* src) {
    unsigned d = (unsigned)__cvta_generic_to_shared(dst);
    asm volatile("cp.async.cg.shared.global [%0], [%1], 16;\n" :: "r"(d), "l"(src));
}
__device__ __forceinline__ void cp_commit() {
    asm volatile("cp.async.commit_group;\n");
}
template<int N>
__device__ __forceinline__ void cp_wait() {
    asm volatile("cp.async.wait_group %0;\n" :: "n"(N));
}
__device__ __forceinline__ void ldsm4(unsigned& r0, unsigned& r1,
                                      unsigned& r2, unsigned& r3, unsigned addr) {
    asm volatile("ldmatrix.sync.aligned.m8n8.x4.shared.b16 {%0,%1,%2,%3}, [%4];"
                 : "=r"(r0), "=r"(r1), "=r"(r2), "=r"(r3) : "r"(addr));
}
__device__ __forceinline__ void mma16816(float* acc, const unsigned* a, const unsigned* b) {
    asm volatile(
        "mma.sync.aligned.m16n8k16.row.col.f32.f16.f16.f32 "
        "{%0,%1,%2,%3}, {%4,%5,%6,%7}, {%8,%9}, {%0,%1,%2,%3};"
        : "+f"(acc[0]), "+f"(acc[1]), "+f"(acc[2]), "+f"(acc[3])
        : "r"(a[0]), "r"(a[1]), "r"(a[2]), "r"(a[3]), "r"(b[0]), "r"(b[1]));
}

// ---------------- warp-per-row fused embedding + first LN (fp16 xn out) ----------
__global__ void embed_ln_kernel(const int* __restrict__ ids,
                                const float* __restrict__ tok,
                                const float* __restrict__ pos,
                                const float* __restrict__ lw,
                                const float* __restrict__ lb,
                                float* __restrict__ x,
                                __half* __restrict__ xn) {
    int wid = threadIdx.x >> 5, lane = threadIdx.x & 31;
    int t = blockIdx.x * 8 + wid;
    int id = ids[t];
    int l  = t & (LL - 1);
    const float4* tr = (const float4*)(tok + (size_t)id * DD);
    const float4* pr = (const float4*)(pos + (size_t)l  * DD);
    float4 v[4];
    float s = 0.f, s2 = 0.f;
    #pragma unroll
    for (int j = 0; j < 4; j++) {
        float4 a = tr[j * 32 + lane];
        float4 p = pr[j * 32 + lane];
        v[j].x = a.x + p.x; v[j].y = a.y + p.y;
        v[j].z = a.z + p.z; v[j].w = a.w + p.w;
        s  += v[j].x + v[j].y + v[j].z + v[j].w;
        s2 += v[j].x*v[j].x + v[j].y*v[j].y + v[j].z*v[j].z + v[j].w*v[j].w;
    }
    float4* xr = (float4*)(x + (size_t)t * DD);
    #pragma unroll
    for (int j = 0; j < 4; j++) xr[j * 32 + lane] = v[j];
    #pragma unroll
    for (int o = 16; o; o >>= 1) {
        s  += __shfl_xor_sync(0xffffffffu, s,  o);
        s2 += __shfl_xor_sync(0xffffffffu, s2, o);
    }
    float mean = s * (1.0f / DD);
    float var  = s2 * (1.0f / DD) - mean * mean;
    float inv  = rsqrtf(var + 1e-5f);
    __half* outr = xn + (size_t)t * DD;
    #pragma unroll
    for (int j = 0; j < 4; j++) {
        int c = (j * 32 + lane) * 4;
        float4 wv = *(const float4*)(lw + c);
        float4 bv = *(const float4*)(lb + c);
        __half2 h0 = __floats2half2_rn((v[j].x - mean) * inv * wv.x + bv.x,
                                       (v[j].y - mean) * inv * wv.y + bv.y);
        __half2 h1 = __floats2half2_rn((v[j].z - mean) * inv * wv.z + bv.z,
                                       (v[j].w - mean) * inv * wv.w + bv.w);
        uint2 pk; pk.x = *(unsigned*)&h0; pk.y = *(unsigned*)&h1;
        *(uint2*)(outr + c) = pk;
    }
}

// ---------------- warp-per-row LayerNorm -> fp16 out ----------------
__global__ void ln_kernel(const float* __restrict__ x,
                          const float* __restrict__ w,
                          const float* __restrict__ b,
                          __half* __restrict__ out) {
    int wid = threadIdx.x >> 5, lane = threadIdx.x & 31;
    size_t row = (size_t)blockIdx.x * 8 + wid;
    const float4* xr = (const float4*)(x + row * DD);
    float4 v[4];
    float s = 0.f, s2 = 0.f;
    #pragma unroll
    for (int j = 0; j < 4; j++) {
        v[j] = xr[j * 32 + lane];
        s  += v[j].x + v[j].y + v[j].z + v[j].w;
        s2 += v[j].x*v[j].x + v[j].y*v[j].y + v[j].z*v[j].z + v[j].w*v[j].w;
    }
    #pragma unroll
    for (int o = 16; o; o >>= 1) {
        s  += __shfl_xor_sync(0xffffffffu, s,  o);
        s2 += __shfl_xor_sync(0xffffffffu, s2, o);
    }
    float mean = s * (1.0f / DD);
    float var  = s2 * (1.0f / DD) - mean * mean;
    float inv  = rsqrtf(var + 1e-5f);
    __half* outr = out + row * DD;
    #pragma unroll
    for (int j = 0; j < 4; j++) {
        int c = (j * 32 + lane) * 4;
        float4 wv = *(const float4*)(w + c);
        float4 bv = *(const float4*)(b + c);
        __half2 h0 = __floats2half2_rn((v[j].x - mean) * inv * wv.x + bv.x,
                                       (v[j].y - mean) * inv * wv.y + bv.y);
        __half2 h1 = __floats2half2_rn((v[j].z - mean) * inv * wv.z + bv.z,
                                       (v[j].w - mean) * inv * wv.w + bv.w);
        uint2 pk; pk.x = *(unsigned*)&h0; pk.y = *(unsigned*)&h1;
        *(uint2*)(outr + c) = pk;
    }
}

// ------- merged weight prep: z<2 transp w1 ; z<4 transp w2 ; z==4 pack -------
__global__ void prep_kernel(const float* __restrict__ w1,
                            const float* __restrict__ w2,
                            const float* __restrict__ Wa,
                            const float* __restrict__ Wb,
                            const float* __restrict__ Wc,
                            __half* __restrict__ w1t,
                            __half* __restrict__ w2t,
                            __half* __restrict__ wt) {
    int z = blockIdx.z;
    int tx = threadIdx.x, ty = threadIdx.y;
    if (z == 4) {
        int bx = blockIdx.y * 32 + blockIdx.x;
        if (bx >= 128) return;
        int i = bx * 256 + ty * 32 + tx;
        int d = i >> 6, c = i & 63;
        wt[(size_t)c * DD + d]         = __float2half_rn(Wa[i]);
        wt[(size_t)(64 + c) * DD + d]  = __float2half_rn(Wb[i]);
        wt[(size_t)(128 + c) * DD + d] = __float2half_rn(Wc[i]);
        return;
    }
    __shared__ __half t[32][33];
    const float* in; __half* out; int K, N;
    if (z < 2) {
        if (blockIdx.y >= DD / 32) return;
        K = DD; N = HH;
        in  = w1  + (size_t)z * DD * HH;
        out = w1t + (size_t)z * HH * DD;
    } else {
        if (blockIdx.x >= DD / 32) return;
        K = HH; N = DD;
        in  = w2  + (size_t)(z - 2) * HH * DD;
        out = w2t + (size_t)(z - 2) * DD * HH;
    }
    int n0 = blockIdx.x * 32, k0 = blockIdx.y * 32;
    #pragma unroll
    for (int i = 0; i < 32; i += 8)
        t[ty + i][tx] = __float2half_rn(in[(size_t)(k0 + ty + i) * N + n0 + tx]);
    __syncthreads();
    #pragma unroll
    for (int i = 0; i < 32; i += 8)
        out[(size_t)(n0 + ty + i) * K + k0 + tx] = t[tx][ty + i];
}

// ======= h16gemm2: 128xBN, BK=64, ldmatrix, 2-stage cp.async, OCC CTAs/SM =======
// EPI: 1 bias+exact GELU -> half, 2 bias+residual add -> fp32, 3 tanh -> fp32
template<int BN, int EPI, int OCC>
__global__ __launch_bounds__(256, OCC)
void h16gemm2(const __half* __restrict__ A, const __half* __restrict__ Bw,
              const float* __restrict__ bias, void* __restrict__ Cv,
              int K, int ldc) {
    constexpr int BM = 128, BK = 64;
    constexpr int LDA = BK + 8;
    constexpr int NI  = BN / 16;
    constexpr int NP  = BN / 32;
    constexpr int ASZ = BM * LDA;
    constexpr int BSZ = BN * LDA;
    constexpr int STG = ASZ + BSZ;

    extern __shared__ __half smh[];

    const int tid  = threadIdx.x;
    const int lane = tid & 31, warp = tid >> 5;
    const int wr   = warp >> 1, wc = warp & 1;
    const int g    = lane >> 2, tig = lane & 3;
    const int rowBase = blockIdx.y * BM;
    const int colBase = blockIdx.x * BN;

    float acc[2][NI][4];
    #pragma unroll
    for (int mi = 0; mi < 2; mi++)
        #pragma unroll
        for (int ni = 0; ni < NI; ni++)
            #pragma unroll
            for (int r = 0; r < 4; r++) acc[mi][ni][r] = 0.f;

    unsigned aBase[2], bBase[NP];
    {
        unsigned s0 = (unsigned)__cvta_generic_to_shared(smh);
        #pragma unroll
        for (int mi = 0; mi < 2; mi++) {
            int row = wr * 32 + mi * 16 + (lane & 15);
            int col = (lane >> 4) << 3;
            aBase[mi] = s0 + (row * LDA + col) * 2;
        }
        #pragma unroll
        for (int p = 0; p < NP; p++) {
            int row = wc * (BN / 2) + p * 16 + ((lane >> 4) << 3) + (lane & 7);
            int col = ((lane >> 3) & 1) << 3;
            bBase[p] = s0 + (ASZ + row * LDA + col) * 2;
        }
    }

    const int nt = K / BK;

    auto issue = [&](int kt) {
        __half* As = smh + (kt & 1) * STG;
        __half* Bs = As + ASZ;
        int k0 = kt * BK;
        #pragma unroll
        for (int it = 0; it < (BM * 8) / 256; it++) {
            int idx = tid + it * 256;
            int r = idx >> 3, u = (idx & 7) << 3;
            cp16g(As + r * LDA + u, A + (size_t)(rowBase + r) * K + k0 + u);
        }
        #pragma unroll
        for (int it = 0; it < (BN * 8) / 256; it++) {
            int idx = tid + it * 256;
            int r = idx >> 3, u = (idx & 7) << 3;
            cp16g(Bs + r * LDA + u, Bw + (size_t)(colBase + r) * K + k0 + u);
        }
    };

    issue(0); cp_commit();

    for (int kt = 0; kt < nt; kt++) {
        cp_wait<0>();
        __syncthreads();
        if (kt + 1 < nt) { issue(kt + 1); cp_commit(); }

        unsigned stOff = (unsigned)((kt & 1) * STG * 2);

        #pragma unroll
        for (int kk = 0; kk < BK; kk += 16) {
            unsigned af[2][4];
            #pragma unroll
            for (int mi = 0; mi < 2; mi++)
                ldsm4(af[mi][0], af[mi][1], af[mi][2], af[mi][3],
                      aBase[mi] + stOff + kk * 2);
            unsigned bf[NI][2];
            #pragma unroll
            for (int p = 0; p < NP; p++)
                ldsm4(bf[2*p][0], bf[2*p][1], bf[2*p+1][0], bf[2*p+1][1],
                      bBase[p] + stOff + kk * 2);
            #pragma unroll
            for (int mi = 0; mi < 2; mi++)
                #pragma unroll
                for (int ni = 0; ni < NI; ni++)
                    mma16816(acc[mi][ni], af[mi], bf[ni]);
        }
    }

    #pragma unroll
    for (int mi = 0; mi < 2; mi++) {
        #pragma unroll
        for (int ni = 0; ni < NI; ni++) {
            int row = rowBase + wr * 32 + mi * 16 + g;
            int col = colBase + wc * (BN / 2) + ni * 8 + tig * 2;
            #pragma unroll
            for (int half_ = 0; half_ < 2; half_++) {
                int r = row + half_ * 8;
                float v0 = acc[mi][ni][half_ * 2 + 0];
                float v1 = acc[mi][ni][half_ * 2 + 1];
                if (EPI == 1) {
                    v0 += bias[col];  v1 += bias[col + 1];
                    __half* p = (__half*)Cv + (size_t)r * ldc + col;
                    *(__half2*)p = __floats2half2_rn(v0 * normcdff(v0),
                                                     v1 * normcdff(v1));
                } else if (EPI == 2) {
                    float2* p = (float2*)((float*)Cv + (size_t)r * ldc + col);
                    float2 old = *p;
                    float2 o; o.x = old.x + v0 + bias[col];
                    o.y = old.y + v1 + bias[col + 1];
                    *p = o;
                } else {                             // tanh -> fp32
                    float2* p = (float2*)((float*)Cv + (size_t)r * ldc + col);
                    float2 o; o.x = tanhf(v0); o.y = tanhf(v1);
                    *p = o;
                }
            }
        }
    }
}

// ------- fused u = abc @ class^T + parallel sub-segment triplet scan -------
__global__ void uscan_kernel(const float* __restrict__ abc,
                             const float* __restrict__ cA,
                             const float* __restrict__ cB,
                             const float* __restrict__ cC,
                             float* __restrict__ segout) {
    extern __shared__ float us[];
    float* At  = us;                        // 64*68
    float* Ct  = us + 64*68;                // 64*68
    float* Ut  = us + 2*64*68;              // 64*192
    float* Sub = us + 2*64*68 + 64*192;     // 4 subs x 6 x 64
    const int tid = threadIdx.x;
    const int t0  = blockIdx.x * 64;
    const int tx = tid & 15, ty = tid >> 4;

    for (int gi = 0; gi < 3; gi++) {
        const float* cls = (gi == 0) ? cA : (gi == 1) ? cB : cC;
        for (int i = tid; i < 4096; i += 256) {
            int c = i >> 6, r = i & 63;
            Ct[r * 68 + c] = cls[i];
        }
        for (int i = tid; i < 4096; i += 256) {
            int tok = i >> 6, r = i & 63;
            At[r * 68 + tok] = abc[(size_t)(t0 + tok) * 192 + gi * 64 + r];
        }
        __syncthreads();
        float acc[4][4];
        #pragma unroll
        for (int i = 0; i < 4; i++)
            #pragma unroll
            for (int j = 0; j < 4; j++) acc[i][j] = 0.f;
        for (int r = 0; r < 64; r++) {
            float4 a = *(const float4*)(At + r * 68 + ty * 4);
            float4 b = *(const float4*)(Ct + r * 68 + tx * 4);
            float av[4] = {a.x, a.y, a.z, a.w};
            float bv[4] = {b.x, b.y, b.z, b.w};
            #pragma unroll
            for (int i = 0; i < 4; i++)
                #pragma unroll
                for (int j = 0; j < 4; j++)
                    acc[i][j] = fmaf(av[i], bv[j], acc[i][j]);
        }
        #pragma unroll
        for (int i = 0; i < 4; i++)
            #pragma unroll
            for (int j = 0; j < 4; j++)
                Ut[(ty * 4 + i) * 192 + gi * 64 + tx * 4 + j] = acc[i][j];
        __syncthreads();
    }

    // ---- phase A: 4 parallel 16-token sub-scans (all 256 threads) ----
    {
        int sub = tid >> 6, c = tid & 63;
        int nTokSeg = ((t0 & (LL - 1)) == LL - SEGL) ? SEGL - 1 : SEGL;
        int i0 = sub * 16;
        int i1 = min(i0 + 16, nTokSeg);
        float pA = 0.f, pB = 0.f, pT = 0.f, AB = 0.f, BC = 0.f, S = 0.f, Cs = 0.f;
        #pragma unroll 4
        for (int i = i0; i < i1; i++) {
            float va = Ut[i * 192 + c];
            float vb = Ut[i * 192 + 64 + c];
            float vc = Ut[i * 192 + 128 + c];
            S  = fmaf(vc, pT, S);
            BC = fmaf(vc, pB, BC);
            pT = fmaf(vb, pA, pT);
            AB = fmaf(vb, pA, AB);
            pB += vb;
            pA += va;
            Cs += vc;
        }
        float* o = Sub + (sub * 6) * 64 + c;
        o[0]   = pA;  o[64]  = pB;  o[128] = Cs;
        o[192] = AB;  o[256] = BC;  o[320] = S;
    }
    __syncthreads();

    // ---- phase B: fold 4 sub-aggregates (threads 0..63) ----
    if (tid < 64) {
        int c = tid;
        float A = 0.f, B = 0.f, C = 0.f, AB = 0.f, BC = 0.f, S = 0.f;
        #pragma unroll
        for (int su = 0; su < 4; su++) {
            const float* o = Sub + (su * 6) * 64 + c;
            float xA = o[0], xB = o[64], xC = o[128];
            float xAB = o[192], xBC = o[256], xS = o[320];
            S  += xS + AB * xC + A * xBC;   // uses pre-update AB, A
            AB += xAB + A * xB;             // uses pre-update A
            BC += xBC + B * xC;             // uses pre-update B
            A += xA;  B += xB;  C += xC;
        }
        int b = t0 >> 11;
        int s = (t0 & (LL - 1)) >> 6;
        float* og = segout + ((size_t)(b * NSEG + s) * 6) * 64 + c;
        og[0]   = A;   og[64]  = B;   og[128] = C;
        og[192] = AB;  og[256] = BC;  og[320] = S;
    }
}

// -------- phase 2: combine segments + fused query LN + query head --------
__global__ void scan_combine_kernel(const float* __restrict__ segout,
                                    const float* __restrict__ x,
                                    const float* __restrict__ lnw,
                                    const float* __restrict__ lnb,
                                    const float* __restrict__ Wq,
                                    const float* __restrict__ bq,
                                    float* __restrict__ out) {
    __shared__ float qn[DD];
    __shared__ float red[2][2];
    int b = blockIdx.x, c = threadIdx.x;
    int warp = c >> 5, lane = c & 31;

    const float* xr = x + ((size_t)b * LL + LL - 1) * DD;
    float4 v0 = ((const float4*)xr)[c * 2];
    float4 v1 = ((const float4*)xr)[c * 2 + 1];
    float s  = v0.x + v0.y + v0.z + v0.w + v1.x + v1.y + v1.z + v1.w;
    float s2 = v0.x*v0.x + v0.y*v0.y + v0.z*v0.z + v0.w*v0.w
             + v1.x*v1.x + v1.y*v1.y + v1.z*v1.z + v1.w*v1.w;
    #pragma unroll
    for (int o = 16; o; o >>= 1) {
        s  += __shfl_down_sync(0xffffffffu, s,  o);
        s2 += __shfl_down_sync(0xffffffffu, s2, o);
    }
    if (!lane) { red[0][warp] = s; red[1][warp] = s2; }
    __syncthreads();
    s  = red[0][0] + red[0][1];
    s2 = red[1][0] + red[1][1];
    float mean = s * (1.0f / DD);
    float var  = s2 * (1.0f / DD) - mean * mean;
    float inv  = rsqrtf(var + 1e-5f);
    {
        int k = c * 8;
        float4 w0 = *(const float4*)(lnw + k);
        float4 w1 = *(const float4*)(lnw + k + 4);
        float4 b0 = *(const float4*)(lnb + k);
        float4 b1 = *(const float4*)(lnb + k + 4);
        qn[k + 0] = (v0.x - mean) * inv * w0.x + b0.x;
        qn[k + 1] = (v0.y - mean) * inv * w0.y + b0.y;
        qn[k + 2] = (v0.z - mean) * inv * w0.z + b0.z;
        qn[k + 3] = (v0.w - mean) * inv * w0.w + b0.w;
        qn[k + 4] = (v1.x - mean) * inv * w1.x + b1.x;
        qn[k + 5] = (v1.y - mean) * inv * w1.y + b1.y;
        qn[k + 6] = (v1.z - mean) * inv * w1.z + b1.z;
        qn[k + 7] = (v1.w - mean) * inv * w1.w + b1.w;
    }
    __syncthreads();

    float PA = 0.f, PAB = 0.f, PE = 0.f, total = 0.f;
    #pragma unroll
    for (int sg = 0; sg < NSEG; sg++) {
        const float* o = segout + ((size_t)(b * NSEG + sg) * 6) * 64 + c;
        float A = o[0], B = o[64], C = o[128], AB = o[192], BC = o[256], S = o[320];
        total += S + C * (PE + PAB) + BC * PA;
        PE  = fmaf(B, PA, PE);
        PAB += AB;
        PA  += A;
    }

    float q = 0.f;
    #pragma unroll 8
    for (int k = 0; k < DD; k++) q = fmaf(qn[k], Wq[k * CC + c], q);
    const float inv_den = (float)(6.0 / (2047.0 * 2046.0 * 2045.0));
    out[b * CC + c] = total * inv_den + q + bq[c];
}

// ---------------- launch ----------------
extern "C" void kernel_launch(void* const* d_in, const int* in_sizes, int n_in,
                              void* d_out, int out_size) {
    const int*   ids       = (const int*)  d_in[0];
    const float* tok_emb   = (const float*)d_in[1];
    const float* pos_emb   = (const float*)d_in[2];
    const float* stem_ln_w = (const float*)d_in[3];
    const float* stem_ln_b = (const float*)d_in[4];
    const float* stem_w1   = (const float*)d_in[5];
    const float* stem_b1   = (const float*)d_in[6];
    const float* stem_w2   = (const float*)d_in[7];
    const float* stem_b2   = (const float*)d_in[8];
    const float* role_ln_w = (const float*)d_in[9];
    const float* role_ln_b = (const float*)d_in[10];
    const float* Wa        = (const float*)d_in[11];
    const float* Wb        = (const float*)d_in[12];
    const float* Wc        = (const float*)d_in[13];
    const float* class_a   = (const float*)d_in[14];
    const float* class_b   = (const float*)d_in[15];
    const float* class_c   = (const float*)d_in[16];
    const float* query_ln_w= (const float*)d_in[17];
    const float* query_ln_b= (const float*)d_in[18];
    const float* Wq        = (const float*)d_in[19];
    const float* bq        = (const float*)d_in[20];
    float* out = (float*)d_out;

    float *xp, *abcp, *segp;
    __half *xnp, *hp, *w1t, *w2t, *wt;
    cudaGetSymbolAddress((void**)&xp,   g_x);
    cudaGetSymbolAddress((void**)&xnp,  g_xn);
    cudaGetSymbolAddress((void**)&hp,   g_h);
    cudaGetSymbolAddress((void**)&abcp, g_abc);
    cudaGetSymbolAddress((void**)&w1t,  g_w1t);
    cudaGetSymbolAddress((void**)&w2t,  g_w2t);
    cudaGetSymbolAddress((void**)&wt,   g_wt);
    cudaGetSymbolAddress((void**)&segp, g_seg);

    constexpr int SM64 = 2 * (128 * 72 + 64 * 72) * 2;             // 55296 B
    constexpr int SMUS = (2 * 64 * 68 + 64 * 192 + 4 * 6 * 64) * 4; // 90112 B
    cudaFuncSetAttribute((const void*)h16gemm2<64,1,4>,
                         cudaFuncAttributeMaxDynamicSharedMemorySize, SM64);
    cudaFuncSetAttribute((const void*)h16gemm2<64,2,4>,
                         cudaFuncAttributeMaxDynamicSharedMemorySize, SM64);
    cudaFuncSetAttribute((const void*)h16gemm2<64,3,4>,
                         cudaFuncAttributeMaxDynamicSharedMemorySize, SM64);
    cudaFuncSetAttribute((const void*)uscan_kernel,
                         cudaFuncAttributeMaxDynamicSharedMemorySize, SMUS);

    // 0. merged weight prep
    prep_kernel<<<dim3(32, 32, 5), dim3(32, 8)>>>(
        stem_w1, stem_w2, Wa, Wb, Wc, w1t, w2t, wt);

    // 1. embedding + LN0 fused (warp-per-row)
    embed_ln_kernel<<<MM/8, 256>>>(ids, tok_emb, pos_emb, stem_ln_w, stem_ln_b, xp, xnp);

    // 2. stem blocks (BN=64 tiles, 4 CTA/SM)
    for (int i = 0; i < 2; i++) {
        if (i > 0)
            ln_kernel<<<MM/8, 256>>>(xp, stem_ln_w + i*DD, stem_ln_b + i*DD, xnp);
        h16gemm2<64,1,4><<<dim3(HH/64, MM/128), 256, SM64>>>(
            xnp, w1t + (size_t)i*HH*DD, stem_b1 + i*HH, hp, DD, HH);
        h16gemm2<64,2,4><<<dim3(DD/64, MM/128), 256, SM64>>>(
            hp, w2t + (size_t)i*DD*HH, stem_b2 + i*DD, xp, HH, DD);
    }

    // 3. role LN (warp-per-row, fp16 out)
    ln_kernel<<<MM/8, 256>>>(xp, role_ln_w, role_ln_b, xnp);

    // 4. abc = tanh(xn @ [Wa|Wb|Wc]) -> fp32
    h16gemm2<64,3,4><<<dim3(3, MM/128), 256, SM64>>>(xnp, wt, nullptr, abcp, DD, 192);

    // 5+7a. fused u GEMM + parallel sub-segment triplet scan
    uscan_kernel<<<MM/64, 256, SMUS>>>(abcp, class_a, class_b, class_c, segp);

    // 7b. combine segments + fused query LN + query head
    scan_combine_kernel<<<BB, CC>>>(segp, xp, query_ln_w, query_ln_b, Wq, bq, out);
}